// round 9
// baseline (speedup 1.0000x reference)
#include <cuda_runtime.h>
#include <math.h>

// Problem constants
#define BB 8
#define TT 2048
#define DIN 256
#define HH 512
#define G4 2048
#define MM (BB*TT)
#define NCTA 96
#define L0N 32
#define NT 512

typedef unsigned long long u64;

// ---------------- device scratch ----------------
__device__ float g_wx0[(size_t)MM * G4];   // 128MB: x@W0^T + (w0_b+u0_b)
__device__ float g_h1[2][HH * BB];         // ping-pong h1 [j*8+b]
__device__ float g_h2[2][HH * BB];         // ping-pong h2
__device__ unsigned g_bar;

// ---------------- dynamic smem (floats) ----------------
// hS [8192] | redS [16][520] | actS [512]
#define OFF_RED 8192
#define OFF_ACT (8192 + 16 * 520)
#define SMEM_FLOATS (OFF_ACT + 512)
#define SMEM_BYTES (SMEM_FLOATS * 4)   // 68096 B

__device__ __forceinline__ u64 pk2(float x) {
    u64 r; asm("mov.b64 %0, {%1, %1};" : "=l"(r) : "f"(x)); return r;
}
__device__ __forceinline__ void fma2(u64& a, u64 b, u64 c) {
    asm("fma.rn.f32x2 %0, %1, %2, %0;" : "+l"(a) : "l"(b), "l"(c));
}
__device__ __forceinline__ u64 addp(u64 a, u64 b) {
    u64 r; asm("add.rn.f32x2 %0, %1, %2;" : "=l"(r) : "l"(a), "l"(b)); return r;
}
__device__ __forceinline__ float4 ldcg4(const float4* p) { return __ldcg(p); }
__device__ __forceinline__ unsigned ldacq(const unsigned* p) {
    unsigned v;
    asm volatile("ld.acquire.gpu.global.u32 %0, [%1];" : "=r"(v) : "l"(p) : "memory");
    return v;
}
__device__ __forceinline__ void release_bar() {
    asm volatile("red.release.gpu.global.add.u32 [%0], 1;" :: "l"(&g_bar) : "memory");
}
__device__ __forceinline__ void pollbar(unsigned tgt) {
    unsigned v;
    do { v = ldacq(&g_bar); } while (v < tgt);
}
__device__ __forceinline__ float fast_sig(float x) {
    return __fdividef(1.f, 1.f + __expf(-x));
}
__device__ __forceinline__ float fast_tanh(float x) {
    float e = __expf(2.f * x);
    return 1.f - __fdividef(2.f, e + 1.f);
}

#define FMA_BLOCK                                                         \
    { const ulonglong2* hp = (const ulonglong2*)(hb + kk * 8);            \
      ulonglong2 hA = hp[0], hB = hp[1];                                  \
      u64 w0 = pk2(wr[2 * kk]), w1 = pk2(wr[2 * kk + 1]);                 \
      fma2(acc[0], w0, hA.x); fma2(acc[1], w0, hA.y);                     \
      fma2(acc[2], w0, hB.x); fma2(acc[3], w0, hB.y);                     \
      fma2(acc[4], w1, hA.x); fma2(acc[5], w1, hA.y);                     \
      fma2(acc[6], w1, hB.x); fma2(acc[7], w1, hB.y); }

__global__ void __launch_bounds__(NT, 1)
lstm_persist(const float* __restrict__ u0w,
             const float* __restrict__ w1w, const float* __restrict__ u1w,
             const float* __restrict__ w1b, const float* __restrict__ u1b,
             float* __restrict__ out)
{
    extern __shared__ float sm[];
    float* hS   = sm;
    float* redS = sm + OFF_RED;
    float* actS = sm + OFF_ACT;

    const int t    = threadIdx.x;
    const int cta  = blockIdx.x;
    const int lane = t & 31;
    const int w    = t >> 5;

    float wr[64];
    u64 acc[8];
    float c_state = 0.f;

    if (cta < L0N) {
        // ======== LAYER 0: U0*h1, 64 rows (16 units x 4 gates), k=512 ========
        const int ubase = cta * 16;
        {
            const int lr0 = 2 * lane, lr1 = lr0 + 1;
            const int g0 = (lr0 >> 4) * 512 + ubase + (lr0 & 15);
            const int g1 = (lr1 >> 4) * 512 + ubase + (lr1 & 15);
            #pragma unroll 8
            for (int kk = 0; kk < 32; ++kk) {
                int k = w * 32 + kk;
                wr[2 * kk]     = u0w[(size_t)g0 * 512 + k];
                wr[2 * kk + 1] = u0w[(size_t)g1 * 512 + k];
            }
        }
        // act role: value t -> row=t>>3, b=t&7, gate=t>>7
        const int arow = t >> 3, ab = t & 7;
        const size_t wxoff = ((size_t)(ab * TT)) * G4 + (arow >> 4) * 512 + ubase + (arow & 15);

        for (int r = 0; r < TT; ++r) {
            float wxv = __ldg(&g_wx0[wxoff + (size_t)r * G4]);  // before poll
            if (r) pollbar(96u * (unsigned)r);
            // warp-local stage: k-slice [32w, 32w+32) x 8b
            {
                const float4* s = (const float4*)g_h1[(r + 1) & 1];
                float4* d = (float4*)hS;
                const int i0 = w * 64 + lane;
                d[i0]      = ldcg4(s + i0);
                d[i0 + 32] = ldcg4(s + i0 + 32);
            }
            __syncwarp();

            #pragma unroll
            for (int i = 0; i < 8; ++i) acc[i] = 0ull;
            const float* hb = hS + w * 256;
            #pragma unroll 16
            for (int kk = 0; kk < 32; ++kk) FMA_BLOCK

            {
                u64* rb = (u64*)(redS + w * 520 + lane * 16);
                #pragma unroll
                for (int i = 0; i < 8; ++i) rb[i] = acc[i];
            }
            __syncthreads();

            {
                float s = wxv;
                #pragma unroll
                for (int k2 = 0; k2 < 16; ++k2) s += redS[k2 * 520 + t];
                actS[t] = ((t >> 7) == 2) ? fast_tanh(s) : fast_sig(s);
            }
            __syncthreads();

            if (t < 128) {
                const int u = t >> 3, b = t & 7;
                float ai = actS[t];
                float af = actS[128 + t];
                float ag = actS[256 + t];
                float ao = actS[384 + t];
                c_state = af * c_state + ai * ag;
                float h = ao * fmaxf(c_state, 0.f);
                const int j = ubase + u;
                __stcg(&g_h1[r & 1][j * 8 + b], h);
                if (r == TT - 1) {
                    out[8388608 + b * 512 + j] = h;        // hh[0]
                    out[8396800 + b * 512 + j] = c_state;  // cc[0]
                }
                asm volatile("bar.sync 1, 128;" ::: "memory");
                if (t == 0) release_bar();
            }
            // warps 4..15 race ahead to next poll (gated by all releases)
        }
    } else {
        // ======== LAYER 1: [W1|U1]*[h1;h2], 32 rows (8 units x 4 gates), k=1024 ========
        const int lcta  = cta - L0N;
        const int ubase = lcta * 8;
        const int jp = lane & 15, ksub = lane >> 4;
        {
            const int lr0 = 2 * jp, lr1 = lr0 + 1;
            const int g0 = (lr0 >> 3) * 512 + ubase + (lr0 & 7);
            const int g1 = (lr1 >> 3) * 512 + ubase + (lr1 & 7);
            #pragma unroll 8
            for (int kk = 0; kk < 32; ++kk) {
                int k = w * 64 + ksub * 32 + kk;
                if (k < 512) {
                    wr[2 * kk]     = w1w[(size_t)g0 * 512 + k];
                    wr[2 * kk + 1] = w1w[(size_t)g1 * 512 + k];
                } else {
                    wr[2 * kk]     = u1w[(size_t)g0 * 512 + (k - 512)];
                    wr[2 * kk + 1] = u1w[(size_t)g1 * 512 + (k - 512)];
                }
            }
        }
        float biasv = 0.f;
        if (t < 256) {
            int gr = (t >> 6) * 512 + ubase + ((t >> 3) & 7);
            biasv = w1b[gr] + u1b[gr];
        }

        for (int r = 0; r <= TT; ++r) {
            const bool active = (r >= 1);
            if (r) pollbar(96u * (unsigned)r);
            if (active) {
                // stage: warps 0-7 h1[r-1] slices, warps 8-15 h2[r-2] slices
                const float4* s1 = (const float4*)g_h1[(r + 1) & 1];
                const float4* s2 = (const float4*)g_h2[r & 1];
                const float4* src = (w < 8) ? (s1 + w * 128) : (s2 + (w - 8) * 128);
                float4* d = (float4*)hS;
                const int base = w * 128 + lane;
                d[base]      = ldcg4(src + lane);
                d[base + 32] = ldcg4(src + lane + 32);
                d[base + 64] = ldcg4(src + lane + 64);
                d[base + 96] = ldcg4(src + lane + 96);
                __syncwarp();

                #pragma unroll
                for (int i = 0; i < 8; ++i) acc[i] = 0ull;
                const float* hb = hS + w * 512 + ksub * 256;
                #pragma unroll 16
                for (int kk = 0; kk < 32; ++kk) FMA_BLOCK

                #pragma unroll
                for (int i = 0; i < 8; ++i)
                    acc[i] = addp(acc[i], __shfl_xor_sync(0xffffffffu, acc[i], 16));
                if (lane < 16) {
                    u64* rb = (u64*)(redS + w * 520 + jp * 16);
                    #pragma unroll
                    for (int i = 0; i < 8; ++i) rb[i] = acc[i];
                }
            }
            __syncthreads();

            if (active && t < 256) {
                float s = biasv;
                #pragma unroll
                for (int k2 = 0; k2 < 16; ++k2) s += redS[k2 * 520 + t];
                actS[t] = ((t >> 6) == 2) ? fast_tanh(s) : fast_sig(s);
            }
            __syncthreads();

            if (active && t < 64) {
                const int u = t >> 3, b = t & 7;
                float ai = actS[t];
                float af = actS[64 + t];
                float ag = actS[128 + t];
                float ao = actS[192 + t];
                c_state = af * c_state + ai * ag;
                float h = ao * fmaxf(c_state, 0.f);
                const int j = ubase + u;
                __stcg(&g_h2[(r + 1) & 1][j * 8 + b], h);
                out[((size_t)(b * TT + (r - 1))) * HH + j] = h;   // h2 sequence
                if (r == TT) {
                    out[8388608 + 4096 + b * 512 + j] = h;        // hh[1]
                    out[8396800 + 4096 + b * 512 + j] = c_state;  // cc[1]
                }
            }
            if (r < TT) {
                if (active) {
                    if (t < 64) {
                        asm volatile("bar.sync 1, 64;" ::: "memory");
                        if (t == 0) release_bar();
                    }
                } else {
                    if (t == 0) release_bar();
                }
            }
        }
    }
}

// ---------------- kernel 1: wx0 = x @ w0^T + (w0_b + u0_b), plus state reset ----------------
__global__ void wx_gemm(const float* __restrict__ X, const float* __restrict__ W,
                        const float* __restrict__ b0, const float* __restrict__ ub0)
{
    __shared__ float As[16][128];
    __shared__ float Bs[16][128];
    const int bn = blockIdx.x, bm = blockIdx.y;
    const int t = threadIdx.x;

    if (bn == 0 && bm == 0) {
        float* h1f = (float*)g_h1;
        float* h2f = (float*)g_h2;
        for (int i = t; i < 2 * HH * BB; i += 256) { h1f[i] = 0.f; h2f[i] = 0.f; }
        if (t == 0) g_bar = 0u;
    }

    const int tm = t & 15, tn = t >> 4;
    u64 accp[8][4];
    #pragma unroll
    for (int i = 0; i < 8; ++i)
        #pragma unroll
        for (int j = 0; j < 4; ++j) accp[i][j] = 0ull;

    for (int kt = 0; kt < DIN; kt += 16) {
        #pragma unroll
        for (int i = 0; i < 2; ++i) {
            int f = t * 2 + i;
            int row = f >> 2, kq = f & 3;
            float4 a = *(const float4*)&X[(size_t)(bm * 128 + row) * DIN + kt + kq * 4];
            As[kq * 4 + 0][row] = a.x; As[kq * 4 + 1][row] = a.y;
            As[kq * 4 + 2][row] = a.z; As[kq * 4 + 3][row] = a.w;
            float4 bv = *(const float4*)&W[(size_t)(bn * 128 + row) * DIN + kt + kq * 4];
            Bs[kq * 4 + 0][row] = bv.x; Bs[kq * 4 + 1][row] = bv.y;
            Bs[kq * 4 + 2][row] = bv.z; Bs[kq * 4 + 3][row] = bv.w;
        }
        __syncthreads();
        #pragma unroll
        for (int k = 0; k < 16; ++k) {
            float4 a0 = *(const float4*)&As[k][tm * 8];
            float4 a1 = *(const float4*)&As[k][tm * 8 + 4];
            const ulonglong2* bp = (const ulonglong2*)&Bs[k][tn * 8];
            ulonglong2 c01 = bp[0];
            ulonglong2 c23 = bp[1];
            float av[8] = {a0.x, a0.y, a0.z, a0.w, a1.x, a1.y, a1.z, a1.w};
            #pragma unroll
            for (int i = 0; i < 8; ++i) {
                u64 wp = pk2(av[i]);
                fma2(accp[i][0], wp, c01.x);
                fma2(accp[i][1], wp, c01.y);
                fma2(accp[i][2], wp, c23.x);
                fma2(accp[i][3], wp, c23.y);
            }
        }
        __syncthreads();
    }

    const int gbase = bn * 128 + tn * 8;
    float bias[8];
    #pragma unroll
    for (int j = 0; j < 8; ++j) bias[j] = __ldg(&b0[gbase + j]) + __ldg(&ub0[gbase + j]);
    #pragma unroll
    for (int i = 0; i < 8; ++i) {
        const int m = bm * 128 + tm * 8 + i;
        float v[8];
        #pragma unroll
        for (int p = 0; p < 4; ++p) {
            float lo, hi;
            asm("mov.b64 {%0, %1}, %2;" : "=f"(lo), "=f"(hi) : "l"(accp[i][p]));
            v[2 * p] = lo; v[2 * p + 1] = hi;
        }
        float4 o0 = make_float4(v[0] + bias[0], v[1] + bias[1],
                                v[2] + bias[2], v[3] + bias[3]);
        float4 o1 = make_float4(v[4] + bias[4], v[5] + bias[5],
                                v[6] + bias[6], v[7] + bias[7]);
        *(float4*)&g_wx0[(size_t)m * G4 + gbase]     = o0;
        *(float4*)&g_wx0[(size_t)m * G4 + gbase + 4] = o1;
    }
}

extern "C" void kernel_launch(void* const* d_in, const int* in_sizes, int n_in,
                              void* d_out, int out_size)
{
    const float* x    = (const float*)d_in[0];
    const float* w0_w = (const float*)d_in[1];
    const float* w0_b = (const float*)d_in[2];
    const float* u0_w = (const float*)d_in[3];
    const float* u0_b = (const float*)d_in[4];
    const float* w1_w = (const float*)d_in[5];
    const float* w1_b = (const float*)d_in[6];
    const float* u1_w = (const float*)d_in[7];
    const float* u1_b = (const float*)d_in[8];
    float* out = (float*)d_out;

    static int attr_done = 0;
    if (!attr_done) {
        cudaFuncSetAttribute(lstm_persist, cudaFuncAttributeMaxDynamicSharedMemorySize, SMEM_BYTES);
        attr_done = 1;
    }

    wx_gemm<<<dim3(G4 / 128, MM / 128), 256>>>(x, w0_w, w0_b, u0_b);
    lstm_persist<<<NCTA, NT, SMEM_BYTES>>>(u0_w, w1_w, u1_w, w1_b, u1_b, out);
}

// round 10
// speedup vs baseline: 1.1519x; 1.1519x over previous
#include <cuda_runtime.h>
#include <math.h>

// Problem constants
#define BB 8
#define TT 2048
#define DIN 256
#define HH 512
#define G4 2048
#define MM (BB*TT)
#define NCTA 96
#define L0N 32
#define NT 512

typedef unsigned long long u64;

// ---------------- device scratch ----------------
__device__ float g_wx0[(size_t)MM * G4];   // 128MB: x@W0^T + (w0_b+u0_b)
__device__ float g_h1[2][HH * BB];         // ping-pong h1 [j*8+b]
__device__ float g_h2[2][HH * BB];         // ping-pong h2
__device__ unsigned g_flags[NCTA * 32];    // per-CTA progress flag, 128B stride

// ---------------- dynamic smem (floats) ----------------
// hS [8192] | redS [16][520] | actS [512]
#define OFF_RED 8192
#define OFF_ACT (8192 + 16 * 520)
#define SMEM_FLOATS (OFF_ACT + 512)
#define SMEM_BYTES (SMEM_FLOATS * 4)   // 68096 B

__device__ __forceinline__ u64 pk2(float x) {
    u64 r; asm("mov.b64 %0, {%1, %1};" : "=l"(r) : "f"(x)); return r;
}
__device__ __forceinline__ void fma2(u64& a, u64 b, u64 c) {
    asm("fma.rn.f32x2 %0, %1, %2, %0;" : "+l"(a) : "l"(b), "l"(c));
}
__device__ __forceinline__ u64 addp(u64 a, u64 b) {
    u64 r; asm("add.rn.f32x2 %0, %1, %2;" : "=l"(r) : "l"(a), "l"(b)); return r;
}
__device__ __forceinline__ float4 ldcg4(const float4* p) { return __ldcg(p); }
__device__ __forceinline__ unsigned ldacq(const unsigned* p) {
    unsigned v;
    asm volatile("ld.acquire.gpu.global.u32 %0, [%1];" : "=r"(v) : "l"(p) : "memory");
    return v;
}
__device__ __forceinline__ void strel(unsigned* p, unsigned v) {
    asm volatile("st.release.gpu.global.u32 [%0], %1;" :: "l"(p), "r"(v) : "memory");
}
// warp-collective (call from warp 0): wait until all 96 CTA flags >= tgt
__device__ __forceinline__ void poll96(unsigned tgt, int lane) {
    const unsigned* f = g_flags;
    for (;;) {
        unsigned a = ldacq(f + lane * 32);
        unsigned b = ldacq(f + (lane + 32) * 32);
        unsigned c = ldacq(f + (lane + 64) * 32);
        if (__all_sync(0xffffffffu, (a >= tgt) && (b >= tgt) && (c >= tgt))) return;
    }
}
__device__ __forceinline__ float fast_sig(float x) {
    return __fdividef(1.f, 1.f + __expf(-x));
}
__device__ __forceinline__ float fast_tanh(float x) {
    float e = __expf(2.f * x);
    return 1.f - __fdividef(2.f, e + 1.f);
}

#define FMA_BLOCK                                                         \
    { const ulonglong2* hp = (const ulonglong2*)(hb + kk * 8);            \
      ulonglong2 hA = hp[0], hB = hp[1];                                  \
      u64 w0 = pk2(wr[2 * kk]), w1 = pk2(wr[2 * kk + 1]);                 \
      fma2(acc[0], w0, hA.x); fma2(acc[1], w0, hA.y);                     \
      fma2(acc[2], w0, hB.x); fma2(acc[3], w0, hB.y);                     \
      fma2(acc[4], w1, hA.x); fma2(acc[5], w1, hA.y);                     \
      fma2(acc[6], w1, hB.x); fma2(acc[7], w1, hB.y); }

__global__ void __launch_bounds__(NT, 1)
lstm_persist(const float* __restrict__ u0w,
             const float* __restrict__ w1w, const float* __restrict__ u1w,
             const float* __restrict__ w1b, const float* __restrict__ u1b,
             float* __restrict__ out)
{
    extern __shared__ float sm[];
    float* hS   = sm;
    float* redS = sm + OFF_RED;
    float* actS = sm + OFF_ACT;

    const int t    = threadIdx.x;
    const int cta  = blockIdx.x;
    const int lane = t & 31;
    const int w    = t >> 5;

    float wr[64];
    u64 acc[8];
    float c_state = 0.f;

    if (cta < L0N) {
        // ======== LAYER 0: U0*h1, 64 rows (16 units x 4 gates), k=512 ========
        const int ubase = cta * 16;
        {
            const int lr0 = 2 * lane, lr1 = lr0 + 1;
            const int g0 = (lr0 >> 4) * 512 + ubase + (lr0 & 15);
            const int g1 = (lr1 >> 4) * 512 + ubase + (lr1 & 15);
            #pragma unroll 8
            for (int kk = 0; kk < 32; ++kk) {
                int k = w * 32 + kk;
                wr[2 * kk]     = u0w[(size_t)g0 * 512 + k];
                wr[2 * kk + 1] = u0w[(size_t)g1 * 512 + k];
            }
        }
        // act role: value t -> row=t>>3, b=t&7, gate=t>>7
        const int arow = t >> 3, ab = t & 7;
        const size_t wxoff = ((size_t)(ab * TT)) * G4 + (arow >> 4) * 512 + ubase + (arow & 15);

        for (int r = 0; r < TT; ++r) {
            float wxv = __ldg(&g_wx0[wxoff + (size_t)r * G4]);  // before poll
            if (r) {
                if (w == 0) poll96((unsigned)r, lane);
                __syncthreads();
            }
            // warp-local stage: k-slice [32w, 32w+32) x 8b
            {
                const float4* s = (const float4*)g_h1[(r + 1) & 1];
                float4* d = (float4*)hS;
                const int i0 = w * 64 + lane;
                d[i0]      = ldcg4(s + i0);
                d[i0 + 32] = ldcg4(s + i0 + 32);
            }
            __syncwarp();

            #pragma unroll
            for (int i = 0; i < 8; ++i) acc[i] = 0ull;
            const float* hb = hS + w * 256;
            #pragma unroll 16
            for (int kk = 0; kk < 32; ++kk) FMA_BLOCK

            {
                u64* rb = (u64*)(redS + w * 520 + lane * 16);
                #pragma unroll
                for (int i = 0; i < 8; ++i) rb[i] = acc[i];
            }
            __syncthreads();

            {
                float s = wxv;
                #pragma unroll
                for (int k2 = 0; k2 < 16; ++k2) s += redS[k2 * 520 + t];
                actS[t] = ((t >> 7) == 2) ? fast_tanh(s) : fast_sig(s);
            }
            __syncthreads();

            if (t < 128) {
                const int u = t >> 3, b = t & 7;
                float ai = actS[t];
                float af = actS[128 + t];
                float ag = actS[256 + t];
                float ao = actS[384 + t];
                c_state = af * c_state + ai * ag;
                float h = ao * fmaxf(c_state, 0.f);
                const int j = ubase + u;
                __stcg(&g_h1[r & 1][j * 8 + b], h);
                if (r == TT - 1) {
                    out[8388608 + b * 512 + j] = h;        // hh[0]
                    out[8396800 + b * 512 + j] = c_state;  // cc[0]
                }
                asm volatile("bar.sync 1, 128;" ::: "memory");
                if (t == 0) strel(&g_flags[cta * 32], (unsigned)(r + 1));
            }
            // warps 4..15 proceed; next round's top __syncthreads re-converges
        }
    } else {
        // ======== LAYER 1: [W1|U1]*[h1;h2], 32 rows (8 units x 4 gates), k=1024 ========
        const int ubase = (cta - L0N) * 8;
        const int jp = lane & 15, ksub = lane >> 4;
        {
            const int lr0 = 2 * jp, lr1 = lr0 + 1;
            const int g0 = (lr0 >> 3) * 512 + ubase + (lr0 & 7);
            const int g1 = (lr1 >> 3) * 512 + ubase + (lr1 & 7);
            #pragma unroll 8
            for (int kk = 0; kk < 32; ++kk) {
                int k = w * 64 + ksub * 32 + kk;
                if (k < 512) {
                    wr[2 * kk]     = w1w[(size_t)g0 * 512 + k];
                    wr[2 * kk + 1] = w1w[(size_t)g1 * 512 + k];
                } else {
                    wr[2 * kk]     = u1w[(size_t)g0 * 512 + (k - 512)];
                    wr[2 * kk + 1] = u1w[(size_t)g1 * 512 + (k - 512)];
                }
            }
        }
        float biasv = 0.f;
        if (t < 256) {
            int gr = (t >> 6) * 512 + ubase + ((t >> 3) & 7);
            biasv = w1b[gr] + u1b[gr];
        }

        for (int r = 0; r <= TT; ++r) {
            const bool active = (r >= 1);
            if (r) {
                if (w == 0) poll96((unsigned)r, lane);
                __syncthreads();
            }
            if (active) {
                // stage: warps 0-7 h1[r-1] slices, warps 8-15 h2[r-2] slices
                const float4* s1 = (const float4*)g_h1[(r + 1) & 1];
                const float4* s2 = (const float4*)g_h2[r & 1];
                const float4* src = (w < 8) ? (s1 + w * 128) : (s2 + (w - 8) * 128);
                float4* d = (float4*)hS;
                const int base = w * 128 + lane;
                d[base]      = ldcg4(src + lane);
                d[base + 32] = ldcg4(src + lane + 32);
                d[base + 64] = ldcg4(src + lane + 64);
                d[base + 96] = ldcg4(src + lane + 96);
                __syncwarp();

                #pragma unroll
                for (int i = 0; i < 8; ++i) acc[i] = 0ull;
                const float* hb = hS + w * 512 + ksub * 256;
                #pragma unroll 16
                for (int kk = 0; kk < 32; ++kk) FMA_BLOCK

                #pragma unroll
                for (int i = 0; i < 8; ++i)
                    acc[i] = addp(acc[i], __shfl_xor_sync(0xffffffffu, acc[i], 16));
                if (lane < 16) {
                    u64* rb = (u64*)(redS + w * 520 + jp * 16);
                    #pragma unroll
                    for (int i = 0; i < 8; ++i) rb[i] = acc[i];
                }
            }
            __syncthreads();

            if (active && t < 256) {
                float s = biasv;
                #pragma unroll
                for (int k2 = 0; k2 < 16; ++k2) s += redS[k2 * 520 + t];
                actS[t] = ((t >> 6) == 2) ? fast_tanh(s) : fast_sig(s);
            }
            __syncthreads();

            if (active && t < 64) {
                const int u = t >> 3, b = t & 7;
                float ai = actS[t];
                float af = actS[64 + t];
                float ag = actS[128 + t];
                float ao = actS[192 + t];
                c_state = af * c_state + ai * ag;
                float h = ao * fmaxf(c_state, 0.f);
                const int j = ubase + u;
                __stcg(&g_h2[(r + 1) & 1][j * 8 + b], h);
                out[((size_t)(b * TT + (r - 1))) * HH + j] = h;   // h2 sequence
                if (r == TT) {
                    out[8388608 + 4096 + b * 512 + j] = h;        // hh[1]
                    out[8396800 + 4096 + b * 512 + j] = c_state;  // cc[1]
                }
            }
            if (r < TT) {
                if (active) {
                    if (t < 64) {
                        asm volatile("bar.sync 1, 64;" ::: "memory");
                        if (t == 0) strel(&g_flags[cta * 32], (unsigned)(r + 1));
                    }
                } else {
                    if (t == 0) strel(&g_flags[cta * 32], (unsigned)(r + 1));
                }
            }
        }
    }
}

// ---------------- kernel 1: wx0 = x @ w0^T + (w0_b + u0_b), plus state reset ----------------
__global__ void wx_gemm(const float* __restrict__ X, const float* __restrict__ W,
                        const float* __restrict__ b0, const float* __restrict__ ub0)
{
    __shared__ float As[16][128];
    __shared__ float Bs[16][128];
    const int bn = blockIdx.x, bm = blockIdx.y;
    const int t = threadIdx.x;

    if (bn == 0 && bm == 0) {
        float* h1f = (float*)g_h1;
        float* h2f = (float*)g_h2;
        for (int i = t; i < 2 * HH * BB; i += 256) { h1f[i] = 0.f; h2f[i] = 0.f; }
        if (t < NCTA) g_flags[t * 32] = 0u;
    }

    const int tm = t & 15, tn = t >> 4;
    u64 accp[8][4];
    #pragma unroll
    for (int i = 0; i < 8; ++i)
        #pragma unroll
        for (int j = 0; j < 4; ++j) accp[i][j] = 0ull;

    for (int kt = 0; kt < DIN; kt += 16) {
        #pragma unroll
        for (int i = 0; i < 2; ++i) {
            int f = t * 2 + i;
            int row = f >> 2, kq = f & 3;
            float4 a = *(const float4*)&X[(size_t)(bm * 128 + row) * DIN + kt + kq * 4];
            As[kq * 4 + 0][row] = a.x; As[kq * 4 + 1][row] = a.y;
            As[kq * 4 + 2][row] = a.z; As[kq * 4 + 3][row] = a.w;
            float4 bv = *(const float4*)&W[(size_t)(bn * 128 + row) * DIN + kt + kq * 4];
            Bs[kq * 4 + 0][row] = bv.x; Bs[kq * 4 + 1][row] = bv.y;
            Bs[kq * 4 + 2][row] = bv.z; Bs[kq * 4 + 3][row] = bv.w;
        }
        __syncthreads();
        #pragma unroll
        for (int k = 0; k < 16; ++k) {
            float4 a0 = *(const float4*)&As[k][tm * 8];
            float4 a1 = *(const float4*)&As[k][tm * 8 + 4];
            const ulonglong2* bp = (const ulonglong2*)&Bs[k][tn * 8];
            ulonglong2 c01 = bp[0];
            ulonglong2 c23 = bp[1];
            float av[8] = {a0.x, a0.y, a0.z, a0.w, a1.x, a1.y, a1.z, a1.w};
            #pragma unroll
            for (int i = 0; i < 8; ++i) {
                u64 wp = pk2(av[i]);
                fma2(accp[i][0], wp, c01.x);
                fma2(accp[i][1], wp, c01.y);
                fma2(accp[i][2], wp, c23.x);
                fma2(accp[i][3], wp, c23.y);
            }
        }
        __syncthreads();
    }

    const int gbase = bn * 128 + tn * 8;
    float bias[8];
    #pragma unroll
    for (int j = 0; j < 8; ++j) bias[j] = __ldg(&b0[gbase + j]) + __ldg(&ub0[gbase + j]);
    #pragma unroll
    for (int i = 0; i < 8; ++i) {
        const int m = bm * 128 + tm * 8 + i;
        float v[8];
        #pragma unroll
        for (int p = 0; p < 4; ++p) {
            float lo, hi;
            asm("mov.b64 {%0, %1}, %2;" : "=f"(lo), "=f"(hi) : "l"(accp[i][p]));
            v[2 * p] = lo; v[2 * p + 1] = hi;
        }
        float4 o0 = make_float4(v[0] + bias[0], v[1] + bias[1],
                                v[2] + bias[2], v[3] + bias[3]);
        float4 o1 = make_float4(v[4] + bias[4], v[5] + bias[5],
                                v[6] + bias[6], v[7] + bias[7]);
        *(float4*)&g_wx0[(size_t)m * G4 + gbase]     = o0;
        *(float4*)&g_wx0[(size_t)m * G4 + gbase + 4] = o1;
    }
}

extern "C" void kernel_launch(void* const* d_in, const int* in_sizes, int n_in,
                              void* d_out, int out_size)
{
    const float* x    = (const float*)d_in[0];
    const float* w0_w = (const float*)d_in[1];
    const float* w0_b = (const float*)d_in[2];
    const float* u0_w = (const float*)d_in[3];
    const float* u0_b = (const float*)d_in[4];
    const float* w1_w = (const float*)d_in[5];
    const float* w1_b = (const float*)d_in[6];
    const float* u1_w = (const float*)d_in[7];
    const float* u1_b = (const float*)d_in[8];
    float* out = (float*)d_out;

    static int attr_done = 0;
    if (!attr_done) {
        cudaFuncSetAttribute(lstm_persist, cudaFuncAttributeMaxDynamicSharedMemorySize, SMEM_BYTES);
        attr_done = 1;
    }

    wx_gemm<<<dim3(G4 / 128, MM / 128), 256>>>(x, w0_w, w0_b, u0_b);
    lstm_persist<<<NCTA, NT, SMEM_BYTES>>>(u0_w, w1_w, u1_w, w1_b, u1_b, out);
}